// round 12
// baseline (speedup 1.0000x reference)
#include <cuda_runtime.h>
#include <cuda_bf16.h>
#include <cstdint>

#define NROWS 262144
#define DDIM  128

typedef unsigned long long u64;
typedef unsigned int u32;

// ---------------- device scratch (no allocations allowed) ----------------
__device__ float g_e[NROWS];
__device__ float g_sp[NROWS];
__device__ float g_expw[NROWS];
__device__ float g_S_part[2048];
__device__ float g_sumeE_part[2048 * 128];
__device__ float g_seMid[128 * 128];
__device__ float g_SMid[128];
__device__ float g_S;
__device__ float g_Cvec[128];
__device__ float g_bias[128];
__device__ __align__(16) float g_Wn[256 * 132];  // pitched [n][k]: n<128 -> W1[n][k], else W2
__device__ float g_gePart[4096 * 128];
__device__ float g_esumPart[4096];
__device__ float g_ge2[32 * 128];
__device__ float g_esum2[32];
__device__ float g_total;
__device__ float g_invTotal;

// ---------------- packed f32x2 helpers (FFMA2 on sm_103) ----------------
__device__ __forceinline__ void fma2(u64 &d, u64 a, u64 b) {
    asm("fma.rn.f32x2 %0, %1, %2, %0;" : "+l"(d) : "l"(a), "l"(b));
}
__device__ __forceinline__ void unpack2(u64 v, float &x, float &y) {
    asm("mov.b64 {%0, %1}, %2;" : "=f"(x), "=f"(y) : "l"(v));
}
struct alignas(16) U64x2 { u64 lo, hi; };   // one LDS.128 = two f32x2 operands

// ---------------- smem layout for k3 (bytes) ----------------
#define FF_AS     0          // 64 x 128 fp32 (32768 B)
#define FF_BS     32768      // 256 x 132 fp32 (135168 B), k-contiguous pitched
#define B_PITCH   132
#define CVEC_OFF  167936
#define BIAS_OFF  168448
#define WVC_OFF   168960
#define ESM_OFF   169472
#define SPM_OFF   169728
#define WROW_OFF  169984
#define RED_OFF   170240     // 4*128*4 = 2048
#define SM3_BYTES 172288

// ---------------- kernel 0: build pitched Wn[n][k] = [W1 ; W2] ----------------
__global__ void k0_wn(const float* __restrict__ W1, const float* __restrict__ W2) {
    int idx = blockIdx.x * 256 + threadIdx.x;   // 0..32767
    int n = idx >> 7;
    int k = idx & 127;
    g_Wn[n * B_PITCH + k] = (n < 128) ? W1[idx] : W2[idx - 16384];
}

// ---------------- kernel 1: sp, s->e, partial S, partial sum_eE (smem-staged) ----------------
#define K1_STRIDE 129
#define K1_SVW    (128 * K1_STRIDE)
#define K1_EXP    (K1_SVW + 256)
#define K1_FLOATS (K1_EXP + 128)
#define K1_BYTES  (K1_FLOATS * 4)

__global__ __launch_bounds__(128) void k1_pass1(const float* __restrict__ E,
                                                const float* __restrict__ v,
                                                const float* __restrict__ wpa,
                                                const float* __restrict__ bpa) {
    extern __shared__ float s1[];
    float*  Es  = s1;
    float2* svw = (float2*)(s1 + K1_SVW);
    float*  es  = s1 + K1_EXP;

    int t = threadIdx.x;
    int rowbase = blockIdx.x * 128;
    const float4* E4 = (const float4*)E + rowbase * 32;

    #pragma unroll
    for (int i = 0; i < 32; i++) {
        int g4 = t + i * 128;
        int r = g4 >> 5, c4 = g4 & 31;
        float4 val = E4[g4];
        Es[(c4 * 4 + 0) * K1_STRIDE + r] = val.x;
        Es[(c4 * 4 + 1) * K1_STRIDE + r] = val.y;
        Es[(c4 * 4 + 2) * K1_STRIDE + r] = val.z;
        Es[(c4 * 4 + 3) * K1_STRIDE + r] = val.w;
    }
    svw[t] = make_float2(wpa[t], v[t]);
    __syncthreads();

    float sp = 0.f, s = 0.f;
    #pragma unroll 8
    for (int k = 0; k < 128; k++) {
        float ev = Es[k * K1_STRIDE + t];
        float2 c = svw[k];
        s  = fmaf(ev, c.x, s);
        sp = fmaf(ev, c.y, sp);
    }
    s += bpa[0];
    float e = expf(s);       // softmax shift-invariant; exponents tiny
    g_sp[rowbase + t] = sp;
    g_e[rowbase + t]  = e;
    es[t] = e;
    __syncthreads();

    float acc = 0.f;
    #pragma unroll 8
    for (int r = 0; r < 128; r++) acc = fmaf(es[r], Es[t * K1_STRIDE + r], acc);
    g_sumeE_part[blockIdx.x * 128 + t] = acc;

    if (t < 32) {
        float t4 = es[t] + es[t + 32] + es[t + 64] + es[t + 96];
        #pragma unroll
        for (int off = 16; off; off >>= 1) t4 += __shfl_xor_sync(0xffffffffu, t4, off);
        if (t == 0) g_S_part[blockIdx.x] = t4;
    }
}

// ---------------- kernel 2a: parallel fold 2048 partials -> 128 ----------------
__global__ __launch_bounds__(128) void k2a_reduce() {
    int b = blockIdx.x;      // 0..127
    int d = threadIdx.x;     // 0..127
    float p = 0.f;
    #pragma unroll
    for (int j = 0; j < 16; j++) p += g_sumeE_part[(b * 16 + j) * 128 + d];
    g_seMid[b * 128 + d] = p;
    if (d == 0) {
        float s = 0.f;
        #pragma unroll
        for (int j = 0; j < 16; j++) s += g_S_part[b * 16 + j];
        g_SMid[b] = s;
    }
}

// ---------------- kernel 2b: final fold (parallel); Cvec = W2 @ sum_eE; bias; S ----------
__global__ __launch_bounds__(1024) void k2b_reduce(const float* __restrict__ W2,
                                                   const float* __restrict__ b_c1,
                                                   const float* __restrict__ b_c2) {
    __shared__ float red[1024];
    __shared__ float se[128];
    int tid = threadIdx.x;
    int d = tid & 127, h = tid >> 7;          // h = 0..7
    float p = 0.f;
    #pragma unroll
    for (int j = 0; j < 16; j++) p += g_seMid[(h * 16 + j) * 128 + d];
    red[h * 128 + d] = p;
    __syncthreads();
    if (tid < 128) {
        float s = 0.f;
        #pragma unroll
        for (int w = 0; w < 8; w++) s += red[w * 128 + tid];
        se[tid] = s;
    }
    if (tid >= 992) {    // last warp folds S in parallel with se fold
        int l = tid - 992;
        float s = g_SMid[l] + g_SMid[l + 32] + g_SMid[l + 64] + g_SMid[l + 96];
        #pragma unroll
        for (int off = 16; off; off >>= 1) s += __shfl_xor_sync(0xffffffffu, s, off);
        if (l == 0) g_S = s;
    }
    __syncthreads();
    int d2 = tid >> 3, sub = tid & 7;
    const float* wrow = W2 + d2 * 128 + sub * 16;
    const float* serow = se + sub * 16;
    float c = 0.f;
    #pragma unroll
    for (int k = 0; k < 16; k++) c = fmaf(wrow[k], serow[k], c);
    c += __shfl_xor_sync(0xffffffffu, c, 1);
    c += __shfl_xor_sync(0xffffffffu, c, 2);
    c += __shfl_xor_sync(0xffffffffu, c, 4);
    if (sub == 0) {
        g_Cvec[d2] = c;
        g_bias[d2] = b_c1[d2] + b_c2[d2];
    }
}

// ---------------- kernel 3: k-packed FFMA2 GEMM + PI + logits + block partials ----------
// 4096 blocks x 512 threads; tile 64 rows x 256 cols; K=128.
// f32x2 lanes split along K (lo=even k, hi=odd k); fold lo+hi in epilogue.
// Warp wid owns rows wid*4..+3; thread lane tx owns cols n = 32q+tx, q=0..7.
// Epilogue pairing: col j (q) with col j+128 (q+4) in the same thread.
__global__ __launch_bounds__(512, 1)
void k3_main(const float* __restrict__ E,
             const float* __restrict__ wvc,
             const float* __restrict__ bvcp) {
    extern __shared__ char smc[];
    float* As    = (float*)(smc + FF_AS);     // [64 m][128 k]
    float* Bs    = (float*)(smc + FF_BS);     // [256 n][132 k-pitch]
    float* cvecS = (float*)(smc + CVEC_OFF);
    float* biasS = (float*)(smc + BIAS_OFF);
    float* wvcS  = (float*)(smc + WVC_OFF);
    float* esm   = (float*)(smc + ESM_OFF);
    float* spm   = (float*)(smc + SPM_OFF);
    float* wrow  = (float*)(smc + WROW_OFF);
    float* red   = (float*)(smc + RED_OFF);

    int tid = threadIdx.x;
    int tx = tid & 31;
    int wid = tid >> 5;                 // 0..15
    int rowbase = blockIdx.x * 64;

    {   // A: 64x128 = 2048 float4, coalesced
        const float4* E4 = (const float4*)E + rowbase * 32;
        float4* As4 = (float4*)As;
        #pragma unroll
        for (int it = 0; it < 4; it++) As4[tid + it * 512] = E4[tid + it * 512];
        // B: 256*132 = 33792 floats = 8448 float4
        const float4* W4 = (const float4*)g_Wn;
        float4* Bs4 = (float4*)Bs;
        #pragma unroll
        for (int it = 0; it < 17; it++) {
            int i = tid + it * 512;
            if (i < 8448) Bs4[i] = W4[i];
        }
    }
    if (tid < 128) {
        cvecS[tid] = g_Cvec[tid];
        biasS[tid] = g_bias[tid];
        wvcS[tid]  = wvc[tid];
    }
    if (tid < 64) {
        esm[tid] = g_e[rowbase + tid];
        spm[tid] = g_sp[rowbase + tid];
    }
    float Sv  = g_S;
    float bvc = bvcp[0];
    __syncthreads();

    u64 acc[4][8];
    #pragma unroll
    for (int mm = 0; mm < 4; mm++)
        #pragma unroll
        for (int q = 0; q < 8; q++) acc[mm][q] = 0ull;

    const float* Arow = As + (wid * 4) * 128;
    const float* Bbase = Bs + tx * B_PITCH;
    #pragma unroll 4
    for (int k0 = 0; k0 < 128; k0 += 4) {
        U64x2 a[4];
        #pragma unroll
        for (int mm = 0; mm < 4; mm++)
            a[mm] = *(const U64x2*)(Arow + mm * 128 + k0);   // LDS.128, warp-broadcast
        #pragma unroll
        for (int q = 0; q < 8; q++) {
            U64x2 b = *(const U64x2*)(Bbase + q * (32 * B_PITCH) + k0);  // LDS.128, conflict-free
            #pragma unroll
            for (int mm = 0; mm < 4; mm++) {
                fma2(acc[mm][q], a[mm].lo, b.lo);
                fma2(acc[mm][q], a[mm].hi, b.hi);
            }
        }
    }

    // --- epilogue: fold k-halves, PI, logit ---
    #pragma unroll
    for (int mm = 0; mm < 4; mm++) {
        int r = wid * 4 + mm;
        float e_i = esm[r];
        float inv = 1.0f / (Sv - e_i);
        float accp = 0.f;
        #pragma unroll
        for (int q = 0; q < 4; q++) {
            int j = q * 32 + tx;
            float ax, ay, bx, by;
            unpack2(acc[mm][q], ax, ay);
            unpack2(acc[mm][q + 4], bx, by);
            float a  = ax + ay;
            float bb = bx + by;
            float hv = a + (cvecS[j] - e_i * bb) * inv + biasS[j];
            accp += fmaxf(hv, 0.f) * wvcS[j];
        }
        #pragma unroll
        for (int off = 16; off; off >>= 1) accp += __shfl_xor_sync(0xffffffffu, accp, off);
        if (tx == 0) {
            float wv = expf(spm[r] + accp + bvc);
            wrow[r] = wv;
            g_expw[rowbase + r] = wv;
        }
    }
    __syncthreads();

    // --- block partials: ge_part[d] = sum_r w_r * E[r][d] ---
    {
        int d = tid & 127;
        int grp = tid >> 7;          // 0..3 -> 16 rows each
        float g = 0.f;
        #pragma unroll
        for (int rr = 0; rr < 16; rr++) {
            int r = grp * 16 + rr;
            g = fmaf(wrow[r], As[r * 128 + d], g);
        }
        red[grp * 128 + d] = g;
    }
    __syncthreads();
    if (tid < 128)
        g_gePart[blockIdx.x * 128 + tid] =
            red[tid] + red[128 + tid] + red[256 + tid] + red[384 + tid];
    if (tid < 32) {
        float s2 = wrow[tid] + wrow[tid + 32];
        #pragma unroll
        for (int off = 16; off; off >>= 1) s2 += __shfl_xor_sync(0xffffffffu, s2, off);
        if (tid == 0) g_esumPart[blockIdx.x] = s2;
    }
}

// ---------------- kernel 4a: reduce 4096 block partials -> 32 ----------------
__global__ void k4a_reduce() {
    int b0 = blockIdx.x * 128;
    int d = threadIdx.x;    // 128 threads
    float g = 0.f;
    #pragma unroll 8
    for (int j = 0; j < 128; j++) g += g_gePart[(b0 + j) * 128 + d];
    g_ge2[blockIdx.x * 128 + d] = g;
    if (d == 0) {
        float s = 0.f;
        for (int j = 0; j < 128; j++) s += g_esumPart[b0 + j];
        g_esum2[blockIdx.x] = s;
    }
}

// ---------------- kernel 4b: final ge + total (also stores 1/total) ----------------
__global__ void k4b_final(float* ge_out) {
    __shared__ float tot;
    int d = threadIdx.x;    // 128 threads
    float g = 0.f;
    #pragma unroll
    for (int c = 0; c < 32; c++) g += g_ge2[c * 128 + d];
    if (d < 32) {
        float t = g_esum2[d];
        #pragma unroll
        for (int off = 16; off; off >>= 1) t += __shfl_xor_sync(0xffffffffu, t, off);
        if (d == 0) { tot = t; g_total = t; g_invTotal = 1.0f / t; }
    }
    __syncthreads();
    if (ge_out) ge_out[d] = g / tot;
}

// ---------------- kernel 5: attention weights ----------------
__global__ void k5_attn(float* __restrict__ attn_out) {
    int i = blockIdx.x * 1024 + threadIdx.x;
    attn_out[i] = g_expw[i] * g_invTotal;
}

// ---------------- launcher ----------------
extern "C" void kernel_launch(void* const* d_in, const int* in_sizes, int n_in,
                              void* d_out, int out_size) {
    const float* E    = (const float*)d_in[0];
    const float* item = (const float*)d_in[1];
    const float* W1   = (const float*)d_in[2];
    const float* bc1  = (const float*)d_in[3];
    const float* W2   = (const float*)d_in[4];
    const float* bc2  = (const float*)d_in[5];
    const float* wpa  = (const float*)d_in[6];
    const float* bpa  = (const float*)d_in[7];
    const float* wvc  = (const float*)d_in[8];
    const float* bvc  = (const float*)d_in[9];

    float* out = (float*)d_out;
    float* ge_out = nullptr;
    float* attn_out = nullptr;
    if (out_size == NROWS + DDIM)      { ge_out = out; attn_out = out + DDIM; }
    else if (out_size == DDIM)         { ge_out = out; }
    else                               { attn_out = out; }

    cudaFuncSetAttribute(k1_pass1, cudaFuncAttributeMaxDynamicSharedMemorySize, K1_BYTES);
    cudaFuncSetAttribute(k3_main,  cudaFuncAttributeMaxDynamicSharedMemorySize, SM3_BYTES);

    k0_wn<<<128, 256>>>(W1, W2);
    k1_pass1<<<2048, 128, K1_BYTES>>>(E, item, wpa, bpa);
    k2a_reduce<<<128, 128>>>();
    k2b_reduce<<<1, 1024>>>(W2, bc1, bc2);
    k3_main<<<4096, 512, SM3_BYTES>>>(E, wvc, bvc);
    k4a_reduce<<<32, 128>>>();
    k4b_final<<<1, 128>>>(ge_out);
    if (attn_out) k5_attn<<<256, 1024>>>(attn_out);
}

// round 13
// speedup vs baseline: 1.0005x; 1.0005x over previous
#include <cuda_runtime.h>
#include <cuda_bf16.h>
#include <cstdint>

#define NROWS 262144
#define DDIM  128

typedef unsigned long long u64;
typedef unsigned int u32;

// ---------------- device scratch (no allocations allowed) ----------------
__device__ float g_e[NROWS];
__device__ float g_sp[NROWS];
__device__ float g_expw[NROWS];
__device__ float g_S_part[2048];
__device__ float g_sumeE_part[2048 * 128];
__device__ float g_seMid[128 * 128];
__device__ float g_SMid[128];
__device__ float g_S;
__device__ float g_Cvec[128];
__device__ float g_bias[128];
__device__ __align__(16) float g_Wn[256 * 132];  // pitched [n][k]: n<128 -> W1[n][k], else W2
__device__ float g_gePart[4096 * 128];
__device__ float g_esumPart[4096];
__device__ float g_ge2[32 * 128];
__device__ float g_esum2[32];
__device__ float g_total;
__device__ float g_invTotal;

// ---------------- packed f32x2 helpers (FFMA2 on sm_103) ----------------
__device__ __forceinline__ void fma2(u64 &d, u64 a, u64 b) {
    asm("fma.rn.f32x2 %0, %1, %2, %0;" : "+l"(d) : "l"(a), "l"(b));
}
__device__ __forceinline__ void unpack2(u64 v, float &x, float &y) {
    asm("mov.b64 {%0, %1}, %2;" : "=f"(x), "=f"(y) : "l"(v));
}
struct alignas(16) U64x2 { u64 lo, hi; };   // one LDS.128 = two f32x2 operands

// ---------------- smem layout for k3 (bytes) ----------------
#define FF_AS     0          // 64 x 128 fp32 (32768 B)
#define FF_BS     32768      // 256 x 132 fp32 (135168 B), k-contiguous pitched
#define B_PITCH   132
#define CVEC_OFF  167936
#define BIAS_OFF  168448
#define WVC_OFF   168960
#define ESM_OFF   169472
#define SPM_OFF   169728
#define WROW_OFF  169984
#define RED_OFF   170240     // 4*128*4 = 2048
#define SM3_BYTES 172288

// ---------------- kernel 0: build pitched Wn[n][k] = [W1 ; W2] ----------------
__global__ void k0_wn(const float* __restrict__ W1, const float* __restrict__ W2) {
    int idx = blockIdx.x * 256 + threadIdx.x;   // 0..32767
    int n = idx >> 7;
    int k = idx & 127;
    g_Wn[n * B_PITCH + k] = (n < 128) ? W1[idx] : W2[idx - 16384];
}

// ---------------- kernel 1: sp, s->e, partial S, partial sum_eE (smem-staged) ----------------
#define K1_STRIDE 129
#define K1_SVW    (128 * K1_STRIDE)
#define K1_EXP    (K1_SVW + 256)
#define K1_FLOATS (K1_EXP + 128)
#define K1_BYTES  (K1_FLOATS * 4)

__global__ __launch_bounds__(128) void k1_pass1(const float* __restrict__ E,
                                                const float* __restrict__ v,
                                                const float* __restrict__ wpa,
                                                const float* __restrict__ bpa) {
    extern __shared__ float s1[];
    float*  Es  = s1;
    float2* svw = (float2*)(s1 + K1_SVW);
    float*  es  = s1 + K1_EXP;

    int t = threadIdx.x;
    int rowbase = blockIdx.x * 128;
    const float4* E4 = (const float4*)E + rowbase * 32;

    #pragma unroll
    for (int i = 0; i < 32; i++) {
        int g4 = t + i * 128;
        int r = g4 >> 5, c4 = g4 & 31;
        float4 val = E4[g4];
        Es[(c4 * 4 + 0) * K1_STRIDE + r] = val.x;
        Es[(c4 * 4 + 1) * K1_STRIDE + r] = val.y;
        Es[(c4 * 4 + 2) * K1_STRIDE + r] = val.z;
        Es[(c4 * 4 + 3) * K1_STRIDE + r] = val.w;
    }
    svw[t] = make_float2(wpa[t], v[t]);
    __syncthreads();

    float sp = 0.f, s = 0.f;
    #pragma unroll 8
    for (int k = 0; k < 128; k++) {
        float ev = Es[k * K1_STRIDE + t];
        float2 c = svw[k];
        s  = fmaf(ev, c.x, s);
        sp = fmaf(ev, c.y, sp);
    }
    s += bpa[0];
    float e = expf(s);       // softmax shift-invariant; exponents tiny
    g_sp[rowbase + t] = sp;
    g_e[rowbase + t]  = e;
    es[t] = e;
    __syncthreads();

    float acc = 0.f;
    #pragma unroll 8
    for (int r = 0; r < 128; r++) acc = fmaf(es[r], Es[t * K1_STRIDE + r], acc);
    g_sumeE_part[blockIdx.x * 128 + t] = acc;

    if (t < 32) {
        float t4 = es[t] + es[t + 32] + es[t + 64] + es[t + 96];
        #pragma unroll
        for (int off = 16; off; off >>= 1) t4 += __shfl_xor_sync(0xffffffffu, t4, off);
        if (t == 0) g_S_part[blockIdx.x] = t4;
    }
}

// ---------------- kernel 2a: parallel fold 2048 partials -> 128 ----------------
__global__ __launch_bounds__(128) void k2a_reduce() {
    int b = blockIdx.x;      // 0..127
    int d = threadIdx.x;     // 0..127
    float p = 0.f;
    #pragma unroll
    for (int j = 0; j < 16; j++) p += g_sumeE_part[(b * 16 + j) * 128 + d];
    g_seMid[b * 128 + d] = p;
    if (d == 0) {
        float s = 0.f;
        #pragma unroll
        for (int j = 0; j < 16; j++) s += g_S_part[b * 16 + j];
        g_SMid[b] = s;
    }
}

// ---------------- kernel 2b: final fold (parallel); Cvec = W2 @ sum_eE; bias; S ----------
__global__ __launch_bounds__(1024) void k2b_reduce(const float* __restrict__ W2,
                                                   const float* __restrict__ b_c1,
                                                   const float* __restrict__ b_c2) {
    __shared__ float red[1024];
    __shared__ float se[128];
    int tid = threadIdx.x;
    int d = tid & 127, h = tid >> 7;          // h = 0..7
    float p = 0.f;
    #pragma unroll
    for (int j = 0; j < 16; j++) p += g_seMid[(h * 16 + j) * 128 + d];
    red[h * 128 + d] = p;
    __syncthreads();
    if (tid < 128) {
        float s = 0.f;
        #pragma unroll
        for (int w = 0; w < 8; w++) s += red[w * 128 + tid];
        se[tid] = s;
    }
    if (tid >= 992) {    // last warp folds S in parallel with se fold
        int l = tid - 992;
        float s = g_SMid[l] + g_SMid[l + 32] + g_SMid[l + 64] + g_SMid[l + 96];
        #pragma unroll
        for (int off = 16; off; off >>= 1) s += __shfl_xor_sync(0xffffffffu, s, off);
        if (l == 0) g_S = s;
    }
    __syncthreads();
    int d2 = tid >> 3, sub = tid & 7;
    const float* wrow = W2 + d2 * 128 + sub * 16;
    const float* serow = se + sub * 16;
    float c = 0.f;
    #pragma unroll
    for (int k = 0; k < 16; k++) c = fmaf(wrow[k], serow[k], c);
    c += __shfl_xor_sync(0xffffffffu, c, 1);
    c += __shfl_xor_sync(0xffffffffu, c, 2);
    c += __shfl_xor_sync(0xffffffffu, c, 4);
    if (sub == 0) {
        g_Cvec[d2] = c;
        g_bias[d2] = b_c1[d2] + b_c2[d2];
    }
}

// ---------------- kernel 3: k-packed FFMA2 GEMM + PI + logits + block partials ----------
// 4096 blocks x 512 threads; tile 64 rows x 256 cols; K=128.
// f32x2 lanes split along K (lo=even k, hi=odd k); fold lo+hi in epilogue.
// Warp wid owns rows wid*4..+3; thread lane tx owns cols n = 32q+tx, q=0..7.
// Epilogue pairing: col j (q) with col j+128 (q+4) in the same thread.
__global__ __launch_bounds__(512, 1)
void k3_main(const float* __restrict__ E,
             const float* __restrict__ wvc,
             const float* __restrict__ bvcp) {
    extern __shared__ char smc[];
    float* As    = (float*)(smc + FF_AS);     // [64 m][128 k]
    float* Bs    = (float*)(smc + FF_BS);     // [256 n][132 k-pitch]
    float* cvecS = (float*)(smc + CVEC_OFF);
    float* biasS = (float*)(smc + BIAS_OFF);
    float* wvcS  = (float*)(smc + WVC_OFF);
    float* esm   = (float*)(smc + ESM_OFF);
    float* spm   = (float*)(smc + SPM_OFF);
    float* wrow  = (float*)(smc + WROW_OFF);
    float* red   = (float*)(smc + RED_OFF);

    int tid = threadIdx.x;
    int tx = tid & 31;
    int wid = tid >> 5;                 // 0..15
    int rowbase = blockIdx.x * 64;

    {   // A: 64x128 = 2048 float4, coalesced
        const float4* E4 = (const float4*)E + rowbase * 32;
        float4* As4 = (float4*)As;
        #pragma unroll
        for (int it = 0; it < 4; it++) As4[tid + it * 512] = E4[tid + it * 512];
        // B: 256*132 = 33792 floats = 8448 float4
        const float4* W4 = (const float4*)g_Wn;
        float4* Bs4 = (float4*)Bs;
        #pragma unroll
        for (int it = 0; it < 17; it++) {
            int i = tid + it * 512;
            if (i < 8448) Bs4[i] = W4[i];
        }
    }
    if (tid < 128) {
        cvecS[tid] = g_Cvec[tid];
        biasS[tid] = g_bias[tid];
        wvcS[tid]  = wvc[tid];
    }
    if (tid < 64) {
        esm[tid] = g_e[rowbase + tid];
        spm[tid] = g_sp[rowbase + tid];
    }
    float Sv  = g_S;
    float bvc = bvcp[0];
    __syncthreads();

    u64 acc[4][8];
    #pragma unroll
    for (int mm = 0; mm < 4; mm++)
        #pragma unroll
        for (int q = 0; q < 8; q++) acc[mm][q] = 0ull;

    const float* Arow = As + (wid * 4) * 128;
    const float* Bbase = Bs + tx * B_PITCH;
    #pragma unroll 4
    for (int k0 = 0; k0 < 128; k0 += 4) {
        U64x2 a[4];
        #pragma unroll
        for (int mm = 0; mm < 4; mm++)
            a[mm] = *(const U64x2*)(Arow + mm * 128 + k0);   // LDS.128, warp-broadcast
        #pragma unroll
        for (int q = 0; q < 8; q++) {
            U64x2 b = *(const U64x2*)(Bbase + q * (32 * B_PITCH) + k0);  // LDS.128, conflict-free
            #pragma unroll
            for (int mm = 0; mm < 4; mm++) {
                fma2(acc[mm][q], a[mm].lo, b.lo);
                fma2(acc[mm][q], a[mm].hi, b.hi);
            }
        }
    }

    // --- epilogue: fold k-halves, PI, logit ---
    #pragma unroll
    for (int mm = 0; mm < 4; mm++) {
        int r = wid * 4 + mm;
        float e_i = esm[r];
        float inv = 1.0f / (Sv - e_i);
        float accp = 0.f;
        #pragma unroll
        for (int q = 0; q < 4; q++) {
            int j = q * 32 + tx;
            float ax, ay, bx, by;
            unpack2(acc[mm][q], ax, ay);
            unpack2(acc[mm][q + 4], bx, by);
            float a  = ax + ay;
            float bb = bx + by;
            float hv = a + (cvecS[j] - e_i * bb) * inv + biasS[j];
            accp += fmaxf(hv, 0.f) * wvcS[j];
        }
        #pragma unroll
        for (int off = 16; off; off >>= 1) accp += __shfl_xor_sync(0xffffffffu, accp, off);
        if (tx == 0) {
            float wv = expf(spm[r] + accp + bvc);
            wrow[r] = wv;
            g_expw[rowbase + r] = wv;
        }
    }
    __syncthreads();

    // --- block partials: ge_part[d] = sum_r w_r * E[r][d] ---
    {
        int d = tid & 127;
        int grp = tid >> 7;          // 0..3 -> 16 rows each
        float g = 0.f;
        #pragma unroll
        for (int rr = 0; rr < 16; rr++) {
            int r = grp * 16 + rr;
            g = fmaf(wrow[r], As[r * 128 + d], g);
        }
        red[grp * 128 + d] = g;
    }
    __syncthreads();
    if (tid < 128)
        g_gePart[blockIdx.x * 128 + tid] =
            red[tid] + red[128 + tid] + red[256 + tid] + red[384 + tid];
    if (tid < 32) {
        float s2 = wrow[tid] + wrow[tid + 32];
        #pragma unroll
        for (int off = 16; off; off >>= 1) s2 += __shfl_xor_sync(0xffffffffu, s2, off);
        if (tid == 0) g_esumPart[blockIdx.x] = s2;
    }
}

// ---------------- kernel 4a: reduce 4096 block partials -> 32 ----------------
__global__ void k4a_reduce() {
    int b0 = blockIdx.x * 128;
    int d = threadIdx.x;    // 128 threads
    float g = 0.f;
    #pragma unroll 8
    for (int j = 0; j < 128; j++) g += g_gePart[(b0 + j) * 128 + d];
    g_ge2[blockIdx.x * 128 + d] = g;
    if (d == 0) {
        float s = 0.f;
        for (int j = 0; j < 128; j++) s += g_esumPart[b0 + j];
        g_esum2[blockIdx.x] = s;
    }
}

// ---------------- kernel 4b: final ge + total (also stores 1/total) ----------------
__global__ void k4b_final(float* ge_out) {
    __shared__ float tot;
    int d = threadIdx.x;    // 128 threads
    float g = 0.f;
    #pragma unroll
    for (int c = 0; c < 32; c++) g += g_ge2[c * 128 + d];
    if (d < 32) {
        float t = g_esum2[d];
        #pragma unroll
        for (int off = 16; off; off >>= 1) t += __shfl_xor_sync(0xffffffffu, t, off);
        if (d == 0) { tot = t; g_total = t; g_invTotal = 1.0f / t; }
    }
    __syncthreads();
    if (ge_out) ge_out[d] = g / tot;
}

// ---------------- kernel 5: attention weights ----------------
__global__ void k5_attn(float* __restrict__ attn_out) {
    int i = blockIdx.x * 1024 + threadIdx.x;
    attn_out[i] = g_expw[i] * g_invTotal;
}

// ---------------- launcher ----------------
extern "C" void kernel_launch(void* const* d_in, const int* in_sizes, int n_in,
                              void* d_out, int out_size) {
    const float* E    = (const float*)d_in[0];
    const float* item = (const float*)d_in[1];
    const float* W1   = (const float*)d_in[2];
    const float* bc1  = (const float*)d_in[3];
    const float* W2   = (const float*)d_in[4];
    const float* bc2  = (const float*)d_in[5];
    const float* wpa  = (const float*)d_in[6];
    const float* bpa  = (const float*)d_in[7];
    const float* wvc  = (const float*)d_in[8];
    const float* bvc  = (const float*)d_in[9];

    float* out = (float*)d_out;
    float* ge_out = nullptr;
    float* attn_out = nullptr;
    if (out_size == NROWS + DDIM)      { ge_out = out; attn_out = out + DDIM; }
    else if (out_size == DDIM)         { ge_out = out; }
    else                               { attn_out = out; }

    cudaFuncSetAttribute(k1_pass1, cudaFuncAttributeMaxDynamicSharedMemorySize, K1_BYTES);
    cudaFuncSetAttribute(k3_main,  cudaFuncAttributeMaxDynamicSharedMemorySize, SM3_BYTES);

    k0_wn<<<128, 256>>>(W1, W2);
    k1_pass1<<<2048, 128, K1_BYTES>>>(E, item, wpa, bpa);
    k2a_reduce<<<128, 128>>>();
    k2b_reduce<<<1, 1024>>>(W2, bc1, bc2);
    k3_main<<<4096, 512, SM3_BYTES>>>(E, wvc, bvc);
    k4a_reduce<<<32, 128>>>();
    k4b_final<<<1, 128>>>(ge_out);
    if (attn_out) k5_attn<<<256, 1024>>>(attn_out);
}